// round 6
// baseline (speedup 1.0000x reference)
#include <cuda_runtime.h>
#include <math.h>

// z = -exp(a) * x ; out = sparsemax(z, axis=0), x (4096, 8192) f32 row-major.
//
// R5: ONE streaming pass over x (no re-read). Conservative support threshold:
//   pre-pass: m~ = column max over first 512 rows (rows hit L2 again at the
//             start of the main pass). Support always satisfies z > max-1 >=
//             m~-1, so {z > m~-1} is a superset of the support (~25/col).
//   main pass: stream all rows once (__ldcs), write zeros to out (__stcs,
//              correct for all non-support rows), push candidates (z,row).
//   exact max = max over candidates; tau via 14 bisections on (zmax-1, zmax)
//   + Michelot fixed point (exact); scatter support values.
// grid=256 x 512 thr, 2 blocks/SM (all resident): DRAM traffic = 256MB min,
// reduce/solve phases of one block overlap streaming of the co-resident one.
// Every LDG.128/STG.128 covers 4 full 128B lines.

#define WIDTH   8192
#define ROWS    4096
#define THREADS 512
#define NWARPS  16
#define CAP     384        // candidates per column (mean ~25, P(>384) ~ 1e-10)
#define PRE     512        // pre-pass rows

__global__ __launch_bounds__(THREADS, 2)
void sparsemax_1pass_kernel(const float* __restrict__ x,
                            const float* __restrict__ a,
                            float* __restrict__ out)
{
    extern __shared__ char smem_raw[];
    float (*s_bv)[CAP] = reinterpret_cast<float (*)[CAP]>(smem_raw);
    int   (*s_br)[CAP] = reinterpret_cast<int   (*)[CAP]>(smem_raw + 32 * CAP * 4);

    __shared__ float s_wm[NWARPS][32];
    __shared__ float s_thr[32];    // m~ - 1
    __shared__ float s_tau[32];
    __shared__ int   s_cnt[32];

    const int tid   = threadIdx.x;
    const int lane  = tid & 31;
    const int warp  = tid >> 5;
    const int col4  = tid & 7;     // float4 slot within 32-col stripe
    const int rbase = tid >> 3;    // 0..63
    const int c0    = blockIdx.x * 32;
    const float scale = -expf(a[0]);

    const float4* xp = reinterpret_cast<const float4*>(x + c0) + col4;
    float4*       op = reinterpret_cast<float4*>(out + c0) + col4;

    if (tid < 32) s_cnt[tid] = 0;

    // ---- pre-pass: approx column max over rows [0, PRE) ----
    float m0 = -INFINITY, m1 = -INFINITY, m2 = -INFINITY, m3 = -INFINITY;
#pragma unroll
    for (int i = 0; i < PRE / 64; ++i) {
        float4 t = xp[(size_t)(rbase + i * 64) * (WIDTH / 4)];
        m0 = fmaxf(m0, scale * t.x);
        m1 = fmaxf(m1, scale * t.y);
        m2 = fmaxf(m2, scale * t.z);
        m3 = fmaxf(m3, scale * t.w);
    }
    // lanes {l, l+8, l+16, l+24} share col4 -> reduce via xor 8,16
#pragma unroll
    for (int off = 8; off <= 16; off <<= 1) {
        m0 = fmaxf(m0, __shfl_xor_sync(0xffffffffu, m0, off));
        m1 = fmaxf(m1, __shfl_xor_sync(0xffffffffu, m1, off));
        m2 = fmaxf(m2, __shfl_xor_sync(0xffffffffu, m2, off));
        m3 = fmaxf(m3, __shfl_xor_sync(0xffffffffu, m3, off));
    }
    if (lane < 8) {
        s_wm[warp][lane * 4 + 0] = m0;
        s_wm[warp][lane * 4 + 1] = m1;
        s_wm[warp][lane * 4 + 2] = m2;
        s_wm[warp][lane * 4 + 3] = m3;
    }
    __syncthreads();
    if (tid < 32) {
        float mm = s_wm[0][tid];
#pragma unroll
        for (int w = 1; w < NWARPS; ++w) mm = fmaxf(mm, s_wm[w][tid]);
        s_thr[tid] = mm - 1.0f;     // conservative threshold
    }
    __syncthreads();

    float th[4];
#pragma unroll
    for (int c = 0; c < 4; ++c) th[c] = s_thr[col4 * 4 + c];

    // ---- main pass: stream once, write zeros, collect candidates ----
    const float4 zero4 = make_float4(0.f, 0.f, 0.f, 0.f);
    for (int i = 0; i < 64; i += 4) {
        float4 t[4];
        int    rw[4];
#pragma unroll
        for (int u = 0; u < 4; ++u) {
            rw[u] = rbase + (i + u) * 64;
            t[u]  = __ldcs(&xp[(size_t)rw[u] * (WIDTH / 4)]);   // last use
        }
#pragma unroll
        for (int u = 0; u < 4; ++u) {
            float zs[4];
            zs[0] = scale * t[u].x;
            zs[1] = scale * t[u].y;
            zs[2] = scale * t[u].z;
            zs[3] = scale * t[u].w;
            __stcs(&op[(size_t)rw[u] * (WIDTH / 4)], zero4);    // streaming
#pragma unroll
            for (int c = 0; c < 4; ++c) {
                if (zs[c] > th[c]) {
                    int col = col4 * 4 + c;
                    int pos = atomicAdd(&s_cnt[col], 1);
                    if (pos < CAP) { s_bv[col][pos] = zs[c]; s_br[col][pos] = rw[u]; }
                }
            }
        }
    }
    __syncthreads();

    // ---- tau per column: exact max, bisection, Michelot (exact) ----
    if (tid < 32) {
        int n = min(s_cnt[tid], CAP);
        const float* b = s_bv[tid];
        float zmax = -INFINITY;
        for (int j = 0; j < n; ++j) zmax = fmaxf(zmax, b[j]);

        float lo = zmax - 1.0f, hi = zmax;     // tau* in [zmax-1, zmax)
        for (int it = 0; it < 14; ++it) {
            float mid = 0.5f * (lo + hi);
            float g = -1.0f;
            for (int k = 0; k < n; ++k) g += fmaxf(b[k] - mid, 0.0f);
            if (g > 0.0f) lo = mid; else hi = mid;
        }
        float tau = lo;
        for (int it = 0; it < 16; ++it) {
            float sum = 0.0f; int k = 0;
            for (int j = 0; j < n; ++j) {
                float z = b[j];
                if (z > tau) { sum += z; ++k; }
            }
            float tn = (sum - 1.0f) / (float)k;   // k >= 1 (zmax > tau)
            if (tn == tau) break;
            tau = tn;
        }
        s_tau[tid] = tau;
    }
    __syncthreads();

    // ---- scatter support values ----
    {
        const int col = tid & 31;
        const int st  = tid >> 5;     // 0..15
        float tau = s_tau[col];
        int n = min(s_cnt[col], CAP);
        for (int j = st; j < n; j += 16) {
            float v = s_bv[col][j] - tau;
            if (v > 0.0f) out[(size_t)s_br[col][j] * WIDTH + c0 + col] = v;
        }
    }
}

extern "C" void kernel_launch(void* const* d_in, const int* in_sizes, int n_in,
                              void* d_out, int out_size)
{
    const float* x = (const float*)d_in[0];
    const float* a = (const float*)d_in[1];
    float* out     = (float*)d_out;

    const int dyn_smem = 32 * CAP * 8;   // 96KB: values + row indices
    cudaFuncSetAttribute(sparsemax_1pass_kernel,
                         cudaFuncAttributeMaxDynamicSharedMemorySize, dyn_smem);
    sparsemax_1pass_kernel<<<WIDTH / 32, THREADS, dyn_smem>>>(x, a, out);
}

// round 7
// speedup vs baseline: 1.2305x; 1.2305x over previous
#include <cuda_runtime.h>
#include <math.h>

// z = -exp(a) * x ; out = sparsemax(z, axis=0), x (4096, 8192) f32 row-major.
//
// R6: one streaming pass over x, NO cache hints (plain LDG/STG — the .cs
// variants measured 20+ points lower DRAM%), compact candidate buffers
// (u16 row idx) to keep L1D alive at 2 blocks/SM.
//   pre-pass: m~ = column max over first 512 rows (re-read hits L2).
//   main pass: stream all rows once, write zeros to out (correct for all
//              non-support rows), push candidates {z > m~-1} (superset of
//              support since tau >= zmax-1 >= m~-1).
//   tau: exact max over candidates, 14 bisections on (zmax-1, zmax), then
//        Michelot fixed point (exact); scatter support values.
// grid=256 x 512 thr, 2 blocks/SM. Every LDG.128/STG.128 covers 4 full lines.

#define WIDTH   8192
#define ROWS    4096
#define THREADS 512
#define NWARPS  16
#define CAP     384        // candidates per column (mean ~15-25)
#define PRE     512        // pre-pass rows

__global__ __launch_bounds__(THREADS, 2)
void sparsemax_1pass_kernel(const float* __restrict__ x,
                            const float* __restrict__ a,
                            float* __restrict__ out)
{
    extern __shared__ char smem_raw[];
    float          (*s_bv)[CAP] = reinterpret_cast<float (*)[CAP]>(smem_raw);
    unsigned short (*s_br)[CAP] =
        reinterpret_cast<unsigned short (*)[CAP]>(smem_raw + 32 * CAP * 4);

    __shared__ float s_wm[NWARPS][32];
    __shared__ float s_thr[32];    // m~ - 1
    __shared__ float s_tau[32];
    __shared__ int   s_cnt[32];

    const int tid   = threadIdx.x;
    const int lane  = tid & 31;
    const int warp  = tid >> 5;
    const int col4  = tid & 7;     // float4 slot within 32-col stripe
    const int rbase = tid >> 3;    // 0..63
    const int c0    = blockIdx.x * 32;
    const float scale = -expf(a[0]);

    const float4* xp = reinterpret_cast<const float4*>(x + c0) + col4;
    float4*       op = reinterpret_cast<float4*>(out + c0) + col4;

    if (tid < 32) s_cnt[tid] = 0;

    // ---- pre-pass: approx column max over rows [0, PRE) ----
    float m0 = -INFINITY, m1 = -INFINITY, m2 = -INFINITY, m3 = -INFINITY;
#pragma unroll
    for (int i = 0; i < PRE / 64; ++i) {
        float4 t = xp[(size_t)(rbase + i * 64) * (WIDTH / 4)];
        m0 = fmaxf(m0, scale * t.x);
        m1 = fmaxf(m1, scale * t.y);
        m2 = fmaxf(m2, scale * t.z);
        m3 = fmaxf(m3, scale * t.w);
    }
    // lanes {l, l+8, l+16, l+24} share col4 -> reduce via xor 8,16
#pragma unroll
    for (int off = 8; off <= 16; off <<= 1) {
        m0 = fmaxf(m0, __shfl_xor_sync(0xffffffffu, m0, off));
        m1 = fmaxf(m1, __shfl_xor_sync(0xffffffffu, m1, off));
        m2 = fmaxf(m2, __shfl_xor_sync(0xffffffffu, m2, off));
        m3 = fmaxf(m3, __shfl_xor_sync(0xffffffffu, m3, off));
    }
    if (lane < 8) {
        s_wm[warp][lane * 4 + 0] = m0;
        s_wm[warp][lane * 4 + 1] = m1;
        s_wm[warp][lane * 4 + 2] = m2;
        s_wm[warp][lane * 4 + 3] = m3;
    }
    __syncthreads();
    if (tid < 32) {
        float mm = s_wm[0][tid];
#pragma unroll
        for (int w = 1; w < NWARPS; ++w) mm = fmaxf(mm, s_wm[w][tid]);
        s_thr[tid] = mm - 1.0f;     // conservative threshold
    }
    __syncthreads();

    float th[4];
#pragma unroll
    for (int c = 0; c < 4; ++c) th[c] = s_thr[col4 * 4 + c];

    // ---- main pass: stream once, write zeros, collect candidates ----
    const float4 zero4 = make_float4(0.f, 0.f, 0.f, 0.f);
    for (int i = 0; i < 64; i += 4) {
        float4 t[4];
        int    rw[4];
#pragma unroll
        for (int u = 0; u < 4; ++u) {
            rw[u] = rbase + (i + u) * 64;
            t[u]  = xp[(size_t)rw[u] * (WIDTH / 4)];      // plain load
        }
#pragma unroll
        for (int u = 0; u < 4; ++u) {
            float zs[4];
            zs[0] = scale * t[u].x;
            zs[1] = scale * t[u].y;
            zs[2] = scale * t[u].z;
            zs[3] = scale * t[u].w;
            op[(size_t)rw[u] * (WIDTH / 4)] = zero4;      // plain store
#pragma unroll
            for (int c = 0; c < 4; ++c) {
                if (zs[c] > th[c]) {
                    int col = col4 * 4 + c;
                    int pos = atomicAdd(&s_cnt[col], 1);
                    if (pos < CAP) {
                        s_bv[col][pos] = zs[c];
                        s_br[col][pos] = (unsigned short)rw[u];
                    }
                }
            }
        }
    }
    __syncthreads();

    // ---- tau per column: exact max, bisection, Michelot (exact) ----
    if (tid < 32) {
        int n = min(s_cnt[tid], CAP);
        const float* b = s_bv[tid];
        float zmax = -INFINITY;
        for (int j = 0; j < n; ++j) zmax = fmaxf(zmax, b[j]);

        float lo = zmax - 1.0f, hi = zmax;     // tau* in [zmax-1, zmax)
        for (int it = 0; it < 14; ++it) {
            float mid = 0.5f * (lo + hi);
            float g = -1.0f;
            for (int k = 0; k < n; ++k) g += fmaxf(b[k] - mid, 0.0f);
            if (g > 0.0f) lo = mid; else hi = mid;
        }
        float tau = lo;
        for (int it = 0; it < 16; ++it) {
            float sum = 0.0f; int k = 0;
            for (int j = 0; j < n; ++j) {
                float z = b[j];
                if (z > tau) { sum += z; ++k; }
            }
            float tn = (sum - 1.0f) / (float)k;   // k >= 1 (zmax > tau)
            if (tn == tau) break;
            tau = tn;
        }
        s_tau[tid] = tau;
    }
    __syncthreads();

    // ---- scatter support values ----
    {
        const int col = tid & 31;
        const int st  = tid >> 5;     // 0..15
        float tau = s_tau[col];
        int n = min(s_cnt[col], CAP);
        for (int j = st; j < n; j += 16) {
            float v = s_bv[col][j] - tau;
            if (v > 0.0f) out[(size_t)s_br[col][j] * WIDTH + c0 + col] = v;
        }
    }
}

extern "C" void kernel_launch(void* const* d_in, const int* in_sizes, int n_in,
                              void* d_out, int out_size)
{
    const float* x = (const float*)d_in[0];
    const float* a = (const float*)d_in[1];
    float* out     = (float*)d_out;

    const int dyn_smem = 32 * CAP * 4 + 32 * CAP * 2;   // 72KB: values + u16 rows
    cudaFuncSetAttribute(sparsemax_1pass_kernel,
                         cudaFuncAttributeMaxDynamicSharedMemorySize, dyn_smem);
    sparsemax_1pass_kernel<<<WIDTH / 32, THREADS, dyn_smem>>>(x, a, out);
}